// round 8
// baseline (speedup 1.0000x reference)
#include <cuda_runtime.h>
#include <math.h>

// Problem constants
#define Sn 8192
#define Dn 2048
#define En 64
#define Cn 128
#define MAXN 1024   // max tokens gathered per expert (mean 128, sigma ~11)

#define MEGA_BLOCKS 128   // 1 per SM, single wave; 128 x 64 tokens = 8192

static const long long SECn = (long long)Sn * En * Cn;  // 67,108,864

// ---------------- device scratch (no allocations allowed) ----------------
__device__ float g_gate[Sn];                   // gate value at argmax expert
__device__ int   g_expert[Sn];                 // argmax expert per token
__device__ float g_colsum_p[MEGA_BLOCKS][En];  // per-block gate column sums

// packed f32x2 helpers (per-lane identical to fmaf -> bit-faithful logits)
__device__ __forceinline__ unsigned long long pk2(float lo, float hi) {
    unsigned long long r;
    asm("mov.b64 %0, {%1, %2};" : "=l"(r) : "f"(lo), "f"(hi));
    return r;
}
__device__ __forceinline__ void fma2(unsigned long long& d, unsigned long long a,
                                     unsigned long long b) {
    asm("fma.rn.f32x2 %0, %1, %2, %0;" : "+l"(d) : "l"(a), "l"(b));
}
__device__ __forceinline__ void upk2(float& lo, float& hi, unsigned long long v) {
    asm("mov.b64 {%0, %1}, %2;" : "=f"(lo), "=f"(hi) : "l"(v));
}

// ---------------- mega kernel: GEMM + zero-fill + softmax/argmax ----------------
// 128 uniform blocks x 256 threads. Block bid:
//  - computes logits for tokens [bid*64, bid*64+64) x all 64 experts, full K
//    as TWO half-K accumulators (k<1024, k>=1024) summed lo+hi at the end --
//    per-lane fp order identical to the passing split-K + (p0+p1) chain;
//  - interleaves zero-fill of its contiguous 1/128 output slice across all
//    64 k-chunks (uniform-grid overlap, the R3-proven pattern);
//  - epilogue: in-block softmax/argmax on an smem logits tile (same warp
//    reduction code as the previous softmax kernel), writes g_gate/g_expert
//    directly (block owns its tokens -> no atomics) and per-block colsums.
__global__ __launch_bounds__(256, 1) void mega_kernel(const float* __restrict__ x,
                                                      const float* __restrict__ wg,
                                                      float* __restrict__ out,
                                                      long long out_size) {
    __shared__ union {
        struct { float xsT[32][68]; float wsT[32][68]; } t;   // 17.4 KB
        float ls[64][65];                                     // 16.6 KB
    } sm;
    __shared__ float scs[En];

    const int bid = blockIdx.x;
    const int tid = threadIdx.x;
    const int m0 = bid * 64;
    const int tx = tid & 15;    // expert group (4 experts)
    const int ty = tid >> 4;    // token group (4 tokens)

    const long long n4 = out_size >> 2;             // float4 count
    const long long fs = (n4 + MEGA_BLOCKS - 1) >> 7;
    const long long lo = (long long)bid * fs;
    long long hi = lo + fs; if (hi > n4) hi = n4;
    const long long pc = (fs + 63) >> 6;            // per-chunk fill quota
    const float4 z4 = make_float4(0.f, 0.f, 0.f, 0.f);

    // acc[half][tokpair][expert] : f32x2 (lo = token ty*4+2p, hi = +1)
    unsigned long long acc[2][2][4];
#pragma unroll
    for (int h = 0; h < 2; h++)
#pragma unroll
        for (int p = 0; p < 2; p++)
#pragma unroll
            for (int j = 0; j < 4; j++) acc[h][p][j] = 0ull;

#pragma unroll
    for (int half = 0; half < 2; half++) {
        for (int kb = 0; kb < 1024; kb += 32) {
            const int kglob = half * 1024 + kb;
            // load x tile (64 tok x 32 K) and w tile (64 exp x 32 K), transposed
#pragma unroll
            for (int i = 0; i < 2; i++) {
                int v = tid + i * 256;       // 0..511
                int row = v >> 3;            // 0..63
                int kq = v & 7;              // float4 along K
                const float4 xv = *(const float4*)(x + (size_t)(m0 + row) * Dn + (kglob + (kq << 2)));
                sm.t.xsT[(kq << 2) + 0][row] = xv.x;
                sm.t.xsT[(kq << 2) + 1][row] = xv.y;
                sm.t.xsT[(kq << 2) + 2][row] = xv.z;
                sm.t.xsT[(kq << 2) + 3][row] = xv.w;
                const float4 wv = *(const float4*)(wg + (size_t)row * Dn + (kglob + (kq << 2)));
                sm.t.wsT[(kq << 2) + 0][row] = wv.x;
                sm.t.wsT[(kq << 2) + 1][row] = wv.y;
                sm.t.wsT[(kq << 2) + 2][row] = wv.z;
                sm.t.wsT[(kq << 2) + 3][row] = wv.w;
            }
            __syncthreads();

            // interleaved zero-fill: chunk c of 64
            {
                int c = half * 32 + (kb >> 5);
                long long s0 = lo + (long long)c * pc;
                long long s1 = s0 + pc; if (s1 > hi) s1 = hi;
                for (long long i = s0 + tid; i < s1; i += 256)
                    *(float4*)(out + (i << 2)) = z4;
            }

#pragma unroll
            for (int kk = 0; kk < 32; kk++) {
                float4 a = *(const float4*)&sm.t.xsT[kk][ty << 2];
                float4 b = *(const float4*)&sm.t.wsT[kk][tx << 2];
                unsigned long long av2[2] = {pk2(a.x, a.y), pk2(a.z, a.w)};
                unsigned long long bv2[4] = {pk2(b.x, b.x), pk2(b.y, b.y),
                                             pk2(b.z, b.z), pk2(b.w, b.w)};
#pragma unroll
                for (int p = 0; p < 2; p++)
#pragma unroll
                    for (int j = 0; j < 4; j++)
                        fma2(acc[half][p][j], av2[p], bv2[j]);
            }
            __syncthreads();
        }
    }

    // logits = half0 + half1 (same order as previous p0[lane]+p1[lane])
#pragma unroll
    for (int p = 0; p < 2; p++)
#pragma unroll
        for (int j = 0; j < 4; j++) {
            float la, ha, lb, hb;
            upk2(la, ha, acc[0][p][j]);
            upk2(lb, hb, acc[1][p][j]);
            sm.ls[(ty << 2) + (p << 1) + 0][(tx << 2) + j] = la + lb;
            sm.ls[(ty << 2) + (p << 1) + 1][(tx << 2) + j] = ha + hb;
        }
    __syncthreads();
    if (tid < En) scs[tid] = 0.f;
    __syncthreads();

    // softmax/argmax epilogue: warp w handles tokens w*8..w*8+7
    {
        const int warp = tid >> 5;
        const int lane = tid & 31;
        for (int q = 0; q < 8; q++) {
            const int trow = warp * 8 + q;
            const int s = m0 + trow;
            float v0 = sm.ls[trow][lane];
            float v1 = sm.ls[trow][lane + 32];

            float m = fmaxf(v0, v1);
#pragma unroll
            for (int o = 16; o; o >>= 1) m = fmaxf(m, __shfl_xor_sync(0xffffffffu, m, o));

            float e0 = expf(v0 - m), e1 = expf(v1 - m);
            float ss = e0 + e1;
#pragma unroll
            for (int o = 16; o; o >>= 1) ss += __shfl_xor_sync(0xffffffffu, ss, o);
            float inv = 1.0f / ss;
            float gg0 = e0 * inv, gg1 = e1 * inv;

            float bv; int bi;
            if (v0 >= v1) { bv = v0; bi = lane; } else { bv = v1; bi = lane + 32; }
#pragma unroll
            for (int o = 16; o; o >>= 1) {
                float ov = __shfl_xor_sync(0xffffffffu, bv, o);
                int oi = __shfl_xor_sync(0xffffffffu, bi, o);
                if (ov > bv || (ov == bv && oi < bi)) { bv = ov; bi = oi; }
            }
            float gsel = __shfl_sync(0xffffffffu, (bi < 32) ? gg0 : gg1, bi & 31);

            atomicAdd(&scs[lane], gg0);
            atomicAdd(&scs[lane + 32], gg1);
            if (lane == 0) {
                g_gate[s] = gsel;
                g_expert[s] = bi;
            }
        }
    }
    __syncthreads();
    if (tid < En) g_colsum_p[bid][tid] = scs[tid];

    // scalar tail of the fill (out_size = 1 + 2*SEC + E is odd)
    if (bid == MEGA_BLOCKS - 1 && tid == 0) {
        long long p = n4 << 2;
        if (p < out_size) out[p] = 0.f;
    }
}

// ---------------- exact JAX threefry2x32 noise (partitionable path) ----------------
__device__ __forceinline__ unsigned rotl32(unsigned v, int d) {
    return (v << d) | (v >> (32 - d));
}
__device__ __forceinline__ float jax_noise(int s, int e) {
    unsigned x0 = 0u;
    unsigned x1 = (unsigned)(s * En + e);

    const unsigned ks0 = 0u;
    const unsigned ks1 = 42u;
    const unsigned ks2 = 0u ^ 42u ^ 0x1BD11BDAu;

    x0 += ks0; x1 += ks1;
#define TF_ROUND(R) { x0 += x1; x1 = rotl32(x1, R); x1 ^= x0; }
    TF_ROUND(13) TF_ROUND(15) TF_ROUND(26) TF_ROUND(6)
    x0 += ks1; x1 += ks2 + 1u;
    TF_ROUND(17) TF_ROUND(29) TF_ROUND(16) TF_ROUND(24)
    x0 += ks2; x1 += ks0 + 2u;
    TF_ROUND(13) TF_ROUND(15) TF_ROUND(26) TF_ROUND(6)
    x0 += ks0; x1 += ks1 + 3u;
    TF_ROUND(17) TF_ROUND(29) TF_ROUND(16) TF_ROUND(24)
    x0 += ks1; x1 += ks2 + 4u;
    TF_ROUND(13) TF_ROUND(15) TF_ROUND(26) TF_ROUND(6)
    x0 += ks2; x1 += ks0 + 5u;
#undef TF_ROUND
    unsigned bits = x0 ^ x1;
    return __uint_as_float((bits >> 9) | 0x3F800000u) - 1.0f;
}

// ---------------- capacity selection + scatter + l_aux + exp_counts ----------------
// one block per expert; compacts its token list from g_expert (L2-resident),
// ranks by (noise desc, index asc), slots by token-index rank among kept,
// scatters nonzeros onto the zero-filled output. Also writes exp_counts[e]
// and atomically accumulates its l_aux contribution into out[0] (zeroed by fill).
__global__ __launch_bounds__(256) void capacity_kernel(float* __restrict__ out,
                                                       long long out_size) {
    const int e = blockIdx.x;
    __shared__ int   sidx[MAXN];
    __shared__ float snoi[MAXN];
    __shared__ char  skeep[MAXN];
    __shared__ float cred[MEGA_BLOCKS];
    __shared__ int   scnt;

    if (threadIdx.x == 0) scnt = 0;
    __syncthreads();

    // compact tokens routed to expert e (list order irrelevant: selection
    // compares (noise, token index), both order-independent)
    for (int s = threadIdx.x; s < Sn; s += blockDim.x) {
        if (g_expert[s] == e) {
            int p = atomicAdd(&scnt, 1);
            if (p < MAXN) { sidx[p] = s; snoi[p] = jax_noise(s, e); }
        }
    }
    __syncthreads();
    const int nraw = scnt;
    const int n = nraw < MAXN ? nraw : MAXN;

    // keep = rank < capacity by (noise desc, index asc); lax.top_k is index-stable
    for (int i = threadIdx.x; i < n; i += blockDim.x) {
        char k = 1;
        if (n > Cn) {
            int r = 0;
            float ni = snoi[i];
            int ii = sidx[i];
            for (int jj = 0; jj < n; jj++) {
                float nj = snoi[jj];
                r += (nj > ni) || (nj == ni && sidx[jj] < ii);
            }
            k = (r < Cn) ? 1 : 0;
        }
        skeep[i] = k;
    }
    __syncthreads();

    // slot = rank by token index among kept (cumsum semantics); scatter outputs
    for (int i = threadIdx.x; i < n; i += blockDim.x) {
        if (!skeep[i]) continue;
        int ii = sidx[i];
        int slot = 0;
        for (int jj = 0; jj < n; jj++) slot += (skeep[jj] && sidx[jj] < ii);
        long long r = (long long)ii * En + e;
        long long p = 1 + r * (long long)Cn + slot;
        if (p < out_size) out[p] = g_gate[ii];
        if (p + SECn < out_size) out[p + SECn] = 1.0f;
    }

    // exp_counts[e]
    if (threadIdx.x == 0) {
        long long idx = 1 + 2 * SECn + e;
        if (idx < out_size) out[idx] = (float)nraw;
    }

    // l_aux contribution: colsum_e (reduced over block partials) * cnt_e * E/S^2
    if (threadIdx.x < MEGA_BLOCKS) cred[threadIdx.x] = g_colsum_p[threadIdx.x][e];
    __syncthreads();
    if (threadIdx.x == 0) {
        float cs = 0.f;
        for (int i = 0; i < MEGA_BLOCKS; i++) cs += cred[i];
        float contrib = cs * (float)nraw * ((float)En / ((float)Sn * (float)Sn));
        if (out_size > 0) atomicAdd(out, contrib);
    }
}

// ---------------- launch ----------------
extern "C" void kernel_launch(void* const* d_in, const int* in_sizes, int n_in,
                              void* d_out, int out_size) {
    const float* x  = (const float*)d_in[0];   // [S, D] f32
    const float* wg = (const float*)d_in[1];   // [E, D] f32
    float* out = (float*)d_out;
    long long osz = (long long)out_size;

    mega_kernel<<<MEGA_BLOCKS, 256>>>(x, wg, out, osz);
    capacity_kernel<<<En, 256>>>(out, osz);
}

// round 9
// speedup vs baseline: 1.2792x; 1.2792x over previous
#include <cuda_runtime.h>
#include <math.h>

// Problem constants
#define Sn 8192
#define Dn 2048
#define En 64
#define Cn 128
#define MAXN 1024   // max tokens gathered per expert (mean 128, sigma ~11)

static const long long SECn = (long long)Sn * En * Cn;  // 67,108,864

// ---------------- device scratch (no allocations allowed) ----------------
__device__ float g_part[2 * Sn * En];   // split-K partial logits, 4MB
__device__ float g_gate[Sn];            // gate value at argmax expert
__device__ int   g_list[En * MAXN];     // per-expert gathered token indices
__device__ float g_colsum[En];          // column sums of gates (for me)
__device__ int   g_cnt[En];             // raw expert counts (mask1 sums)

// packed f32x2 helpers (per-lane identical to fmaf -> bit-faithful logits)
__device__ __forceinline__ unsigned long long pk2(float lo, float hi) {
    unsigned long long r;
    asm("mov.b64 %0, {%1, %2};" : "=l"(r) : "f"(lo), "f"(hi));
    return r;
}
__device__ __forceinline__ void fma2(unsigned long long& d, unsigned long long a,
                                     unsigned long long b) {
    asm("fma.rn.f32x2 %0, %1, %2, %0;" : "+l"(d) : "l"(a), "l"(b));
}
__device__ __forceinline__ void upk2(float& lo, float& hi, unsigned long long v) {
    asm("mov.b64 {%0, %1}, %2;" : "=f"(lo), "=f"(hi) : "l"(v));
}

// ---------------- fused GEMM + zero-fill (R3 structure, f32x2 compute) ----------------
// 256 uniform blocks x 256 threads (proven best scheduling: every block does
// GEMM chunk + its contiguous 2MB fill chunk, interleaved per k-iteration).
// GEMM: 64 tokens x 64 experts per block, splitK=2 across blocks.
// Inner loop uses fma.rn.f32x2 on token pairs loaded pre-packed from smem
// (2 tokens = consecutive floats in xsT row -> one 16B LDS = 2 packed ops).
// Per-lane fp sequence identical to scalar fmaf chain -> bit-faithful logits.
__global__ __launch_bounds__(256) void gemm_fill_kernel(const float* __restrict__ x,
                                                        const float* __restrict__ wg,
                                                        float* __restrict__ out,
                                                        long long out_size) {
    const int bid = blockIdx.x;          // 0..255
    const int m0 = (bid & 127) * 64;
    const int k0 = (bid >> 7) * 1024;
    __shared__ float xsT[32][68];        // row stride 272B (16B multiple)
    __shared__ float wsT[32][68];

    const int tid = threadIdx.x;
    const int tx = tid & 15;   // expert group (4 experts)
    const int ty = tid >> 4;   // token group (4 tokens = 2 pairs)

    if (bid == 0 && tid < En) {          // init fold-in
        g_colsum[tid] = 0.f;
        g_cnt[tid] = 0;
    }
    if (bid == 0 && tid == 0) {
        long long tail = 2 * SECn;       // dispatch element not covered by fill
        if (tail < out_size) out[tail] = 0.f;
    }

    const size_t fb = (size_t)bid * 524288 + (size_t)(tid << 2);
    const float4 z4 = make_float4(0.f, 0.f, 0.f, 0.f);

    unsigned long long acc2[2][4];       // [token pair][expert], f32x2
#pragma unroll
    for (int p = 0; p < 2; p++)
#pragma unroll
        for (int j = 0; j < 4; j++) acc2[p][j] = 0ull;

    for (int kb = 0; kb < 1024; kb += 32) {
#pragma unroll
        for (int i = 0; i < 2; i++) {
            int v = tid + i * 256;       // 0..511
            int row = v >> 3;            // 0..63
            int kq = v & 7;              // 0..7 (float4 along K)
            const float4 xv = *(const float4*)(x + (size_t)(m0 + row) * Dn + (k0 + kb + (kq << 2)));
            xsT[(kq << 2) + 0][row] = xv.x;
            xsT[(kq << 2) + 1][row] = xv.y;
            xsT[(kq << 2) + 2][row] = xv.z;
            xsT[(kq << 2) + 3][row] = xv.w;
            const float4 wv = *(const float4*)(wg + (size_t)row * Dn + (k0 + kb + (kq << 2)));
            wsT[(kq << 2) + 0][row] = wv.x;
            wsT[(kq << 2) + 1][row] = wv.y;
            wsT[(kq << 2) + 2][row] = wv.z;
            wsT[(kq << 2) + 3][row] = wv.w;
        }
        __syncthreads();

        // interleaved zero-fill: 16 float4 (256B/thread) per k-chunk
        {
            size_t base = fb + (size_t)(kb >> 5) * 16384;  // iter * 16 slots * 1024 floats
#pragma unroll
            for (int q = 0; q < 16; q++)
                *(float4*)(out + base + (size_t)q * 1024) = z4;
        }

#pragma unroll
        for (int kk = 0; kk < 32; kk++) {
            // 4 tokens arrive pre-packed as 2 f32x2 (consecutive floats)
            const ulonglong2 av = *(const ulonglong2*)&xsT[kk][ty << 2];
            const float4 b = *(const float4*)&wsT[kk][tx << 2];
            unsigned long long bv2[4] = {pk2(b.x, b.x), pk2(b.y, b.y),
                                         pk2(b.z, b.z), pk2(b.w, b.w)};
#pragma unroll
            for (int j = 0; j < 4; j++) {
                fma2(acc2[0][j], av.x, bv2[j]);
                fma2(acc2[1][j], av.y, bv2[j]);
            }
        }
        __syncthreads();
    }

    // unpack and store partial logits (same addresses/layout as R3)
    float* op = g_part + (size_t)(bid >> 7) * (Sn * En);
#pragma unroll
    for (int p = 0; p < 2; p++) {
        float l0, h0, l1, h1, l2, h2, l3, h3;
        upk2(l0, h0, acc2[p][0]);
        upk2(l1, h1, acc2[p][1]);
        upk2(l2, h2, acc2[p][2]);
        upk2(l3, h3, acc2[p][3]);
        float4 vlo = make_float4(l0, l1, l2, l3);   // token ty*4 + 2p
        float4 vhi = make_float4(h0, h1, h2, h3);   // token ty*4 + 2p + 1
        *(float4*)(op + (size_t)(m0 + (ty << 2) + 2 * p) * En + (tx << 2)) = vlo;
        *(float4*)(op + (size_t)(m0 + (ty << 2) + 2 * p + 1) * En + (tx << 2)) = vhi;
    }
}

// ---------------- softmax + argmax + column sums + counts + expert lists ----------------
// one warp per token, 8 tokens per block, 1024 blocks
__global__ __launch_bounds__(256) void softmax_kernel() {
    __shared__ float scs[En];
    const int warp = threadIdx.x >> 5;
    const int lane = threadIdx.x & 31;
    const int s = blockIdx.x * 8 + warp;

    if (threadIdx.x < En) scs[threadIdx.x] = 0.f;
    __syncthreads();

    const float* p0 = g_part + (size_t)s * En;
    const float* p1 = g_part + (size_t)(Sn * En) + (size_t)s * En;
    float v0 = p0[lane] + p1[lane];
    float v1 = p0[lane + 32] + p1[lane + 32];

    // row max
    float m = fmaxf(v0, v1);
#pragma unroll
    for (int o = 16; o; o >>= 1) m = fmaxf(m, __shfl_xor_sync(0xffffffffu, m, o));

    float e0 = expf(v0 - m), e1 = expf(v1 - m);
    float ss = e0 + e1;
#pragma unroll
    for (int o = 16; o; o >>= 1) ss += __shfl_xor_sync(0xffffffffu, ss, o);
    float inv = 1.0f / ss;
    float gg0 = e0 * inv, gg1 = e1 * inv;

    // argmax with tie-break: smallest index (matches jnp.argmax)
    float bv; int bi;
    if (v0 >= v1) { bv = v0; bi = lane; } else { bv = v1; bi = lane + 32; }
#pragma unroll
    for (int o = 16; o; o >>= 1) {
        float ov = __shfl_xor_sync(0xffffffffu, bv, o);
        int oi = __shfl_xor_sync(0xffffffffu, bi, o);
        if (ov > bv || (ov == bv && oi < bi)) { bv = ov; bi = oi; }
    }
    // gate value at argmax (bi is warp-uniform now)
    float gsel = __shfl_sync(0xffffffffu, (bi < 32) ? gg0 : gg1, bi & 31);

    // block-level column sums, then one global atomic per expert per block
    atomicAdd(&scs[lane], gg0);
    atomicAdd(&scs[lane + 32], gg1);

    if (lane == 0) {
        g_gate[s] = gsel;
        int p = atomicAdd(&g_cnt[bi], 1);
        if (p < MAXN) g_list[bi * MAXN + p] = s;
    }
    __syncthreads();
    if (threadIdx.x < En) atomicAdd(&g_colsum[threadIdx.x], scs[threadIdx.x]);
}

// ---------------- exact JAX threefry2x32 noise (partitionable path) ----------------
__device__ __forceinline__ unsigned rotl32(unsigned v, int d) {
    return (v << d) | (v >> (32 - d));
}
__device__ __forceinline__ float jax_noise(int s, int e) {
    unsigned x0 = 0u;
    unsigned x1 = (unsigned)(s * En + e);

    const unsigned ks0 = 0u;
    const unsigned ks1 = 42u;
    const unsigned ks2 = 0u ^ 42u ^ 0x1BD11BDAu;

    x0 += ks0; x1 += ks1;
#define TF_ROUND(R) { x0 += x1; x1 = rotl32(x1, R); x1 ^= x0; }
    TF_ROUND(13) TF_ROUND(15) TF_ROUND(26) TF_ROUND(6)
    x0 += ks1; x1 += ks2 + 1u;
    TF_ROUND(17) TF_ROUND(29) TF_ROUND(16) TF_ROUND(24)
    x0 += ks2; x1 += ks0 + 2u;
    TF_ROUND(13) TF_ROUND(15) TF_ROUND(26) TF_ROUND(6)
    x0 += ks0; x1 += ks1 + 3u;
    TF_ROUND(17) TF_ROUND(29) TF_ROUND(16) TF_ROUND(24)
    x0 += ks1; x1 += ks2 + 4u;
    TF_ROUND(13) TF_ROUND(15) TF_ROUND(26) TF_ROUND(6)
    x0 += ks2; x1 += ks0 + 5u;
#undef TF_ROUND
    unsigned bits = x0 ^ x1;
    return __uint_as_float((bits >> 9) | 0x3F800000u) - 1.0f;
}

// ---------------- per-expert capacity selection + direct scatter + finalize ----------------
// one block per expert; reads prebuilt list (fast path, measured ~6us in R3),
// ranks by (noise desc, index asc), slots by token-index rank among kept,
// scatters nonzeros onto zero-filled output. Block 0 writes l_aux + exp_counts.
__global__ __launch_bounds__(256) void capacity_kernel(float* __restrict__ out,
                                                       long long out_size) {
    const int e = blockIdx.x;
    __shared__ int   sidx[MAXN];
    __shared__ float snoi[MAXN];
    __shared__ char  skeep[MAXN];
    __shared__ float sv[En];

    int n = g_cnt[e];
    if (n > MAXN) n = MAXN;

    for (int i = threadIdx.x; i < n; i += blockDim.x) {
        int s = g_list[e * MAXN + i];
        sidx[i] = s;
        snoi[i] = jax_noise(s, e);
    }
    __syncthreads();

    // keep = rank < capacity by (noise desc, index asc); lax.top_k is index-stable
    for (int i = threadIdx.x; i < n; i += blockDim.x) {
        char k = 1;
        if (n > Cn) {
            int r = 0;
            float ni = snoi[i];
            int ii = sidx[i];
            for (int jj = 0; jj < n; jj++) {
                float nj = snoi[jj];
                r += (nj > ni) || (nj == ni && sidx[jj] < ii);
            }
            k = (r < Cn) ? 1 : 0;
        }
        skeep[i] = k;
    }
    __syncthreads();

    // slot = rank by token index among kept (cumsum semantics); scatter outputs
    for (int i = threadIdx.x; i < n; i += blockDim.x) {
        if (!skeep[i]) continue;
        int ii = sidx[i];
        int slot = 0;
        for (int jj = 0; jj < n; jj++) slot += (skeep[jj] && sidx[jj] < ii);
        long long r = (long long)ii * En + e;
        long long p = 1 + r * (long long)Cn + slot;
        if (p < out_size) out[p] = g_gate[ii];
        if (p + SECn < out_size) out[p + SECn] = 1.0f;
    }

    // finalize fold-in: l_aux + exp_counts (block 0 only)
    if (e == 0) {
        int t = threadIdx.x;
        if (t < En) sv[t] = g_colsum[t] * (float)g_cnt[t];
        __syncthreads();
        if (t == 0) {
            float sum = 0.f;
            for (int i = 0; i < En; i++) sum += sv[i];
            float laux = sum * ((float)En / ((float)Sn * (float)Sn));
            if (out_size > 0) out[0] = laux;
        }
        long long idx = 1 + 2 * SECn + t;
        if (t < En && idx < out_size) out[idx] = (float)g_cnt[t];
    }
}

// ---------------- launch ----------------
extern "C" void kernel_launch(void* const* d_in, const int* in_sizes, int n_in,
                              void* d_out, int out_size) {
    const float* x  = (const float*)d_in[0];   // [S, D] f32
    const float* wg = (const float*)d_in[1];   // [E, D] f32
    float* out = (float*)d_out;
    long long osz = (long long)out_size;

    gemm_fill_kernel<<<256, 256>>>(x, wg, out, osz);
    softmax_kernel<<<1024, 256>>>();
    capacity_kernel<<<En, 256>>>(out, osz);
}